// round 14
// baseline (speedup 1.0000x reference)
#include <cuda_runtime.h>

#define BB 32
#define SS 1024
#define DD 512
#define MAXL 8192   // durations in [1,8], S=1024 -> mel_len <= 8192

// 256-bit global load (L1-bypass/nc) and streaming store (sm_100+ PTX v8)
__device__ __forceinline__ void ldg256(const float* p, float* v) {
    asm volatile("ld.global.nc.v8.f32 {%0,%1,%2,%3,%4,%5,%6,%7}, [%8];"
                 : "=f"(v[0]), "=f"(v[1]), "=f"(v[2]), "=f"(v[3]),
                   "=f"(v[4]), "=f"(v[5]), "=f"(v[6]), "=f"(v[7])
                 : "l"(p));
}
__device__ __forceinline__ void stg256_cs(float* p, const float* v) {
    asm volatile("st.global.cs.v8.f32 [%0], {%1,%2,%3,%4,%5,%6,%7,%8};"
                 :: "l"(p),
                    "f"(v[0]), "f"(v[1]), "f"(v[2]), "f"(v[3]),
                    "f"(v[4]), "f"(v[5]), "f"(v[6]), "f"(v[7])
                 : "memory");
}

// warp-level 2-level 32-ary search over smem csum; requires t < mel.
__device__ __forceinline__ int warp_search(const int* s, const int* l1,
                                           int t, int lane)
{
    const int s1 = l1[lane];
    const unsigned m1 = __ballot_sync(0xffffffff, s1 > t);
    const int seg = __ffs(m1) - 1;
    const int s2 = s[(seg << 5) + lane];
    const unsigned m2 = __ballot_sync(0xffffffff, s2 > t);
    return (seg << 5) + __ffs(m2) - 1;   // first i with csum[i] > t
}

// copy-or-zero one output row (straight-line helper)
__device__ __forceinline__ void do_row(const float* __restrict__ x,
                                       const int* s, const int* l1,
                                       float* ob, int bS, int t, int mel,
                                       int lane, const float* z)
{
    if (t >= mel) {
        stg256_cs(ob,       z);
        stg256_cs(ob + 256, z);
    } else {
        const int lo = warp_search(s, l1, t, lane);
        const float* ib = x + ((long)(bS + lo)) * DD + lane * 8;
        float v0[8], v1[8];
        ldg256(ib,       v0);
        ldg256(ib + 256, v1);
        stg256_cs(ob,       v0);
        stg256_cs(ob + 256, v1);
    }
}

// ---------------------------------------------------------------------------
// Single kernel, no inter-block sync. 256 threads = 8 warps; each block
// handles 32 output rows (4 per warp, straight-line), amortizing one smem
// scan of durations[b] across 32 rows.
// ---------------------------------------------------------------------------
__global__ __launch_bounds__(256)
void lr_fused_kernel(const int*   __restrict__ dur,
                     const float* __restrict__ x,
                     float*       __restrict__ out,
                     float*       __restrict__ mel_len_out,
                     float*       __restrict__ mask_out,
                     int max_len, int has_tail)
{
    __shared__ int s[SS];      // inclusive csum of durations[b]
    __shared__ int lvl1[32];   // s[32j+31]
    __shared__ int wsum[8];

    const int b    = blockIdx.y;
    const int tid  = threadIdx.x;
    const int lane = tid & 31;
    const int wid  = tid >> 5;

    // ---- prologue: scan durations[b] into smem (int4/thread) ----
    const int4 d = __ldg(((const int4*)(dur + b * SS)) + tid);
    const int p0 = d.x;
    const int p1 = p0 + d.y;
    const int p2 = p1 + d.z;
    const int p3 = p2 + d.w;
    int tot = p3;
    #pragma unroll
    for (int off = 1; off < 32; off <<= 1) {
        int n = __shfl_up_sync(0xffffffff, tot, off);
        if (lane >= off) tot += n;
    }
    if (lane == 31) wsum[wid] = tot;
    __syncthreads();
    if (wid == 0 && lane < 8) {
        int w = wsum[lane];
        #pragma unroll
        for (int off = 1; off < 8; off <<= 1) {
            int n = __shfl_up_sync(0xff, w, off);
            if (lane >= off) w += n;
        }
        wsum[lane] = w;
    }
    __syncthreads();
    const int base = (tot - p3) + ((wid > 0) ? wsum[wid - 1] : 0);
    s[4 * tid + 0] = base + p0;
    s[4 * tid + 1] = base + p1;
    s[4 * tid + 2] = base + p2;
    s[4 * tid + 3] = base + p3;
    if ((tid & 7) == 7) lvl1[tid >> 3] = base + p3;   // element 32j+31
    __syncthreads();

    // ---- payload: FOUR rows per warp, straight-line ----
    const int t0 = blockIdx.x * 32 + wid * 4;   // rows t0 .. t0+3
    if (t0 >= max_len) return;

    const int mel = lvl1[31];
    const int bS  = b * SS;

    if (has_tail) {
        if (blockIdx.x == 0 && tid == 0) mel_len_out[b] = (float)mel;
        if (lane < 4) {
            const int t = t0 + lane;
            if (t < max_len)
                mask_out[b * max_len + t] = (t >= mel) ? 1.0f : 0.0f;
        }
    }

    const float z[8] = {0.f,0.f,0.f,0.f,0.f,0.f,0.f,0.f};
    float* ob = out + ((long)(b * max_len + t0)) * DD + lane * 8;

    do_row(x, s, lvl1, ob, bS, t0, mel, lane, z);
    if (t0 + 1 < max_len) do_row(x, s, lvl1, ob + DD,     bS, t0 + 1, mel, lane, z);
    if (t0 + 2 < max_len) do_row(x, s, lvl1, ob + 2 * DD, bS, t0 + 2, mel, lane, z);
    if (t0 + 3 < max_len) do_row(x, s, lvl1, ob + 3 * DD, bS, t0 + 3, mel, lane, z);
}

// ---------------------------------------------------------------------------
extern "C" void kernel_launch(void* const* d_in, const int* in_sizes, int n_in,
                              void* d_out, int out_size)
{
    const float* x   = (const float*)d_in[0];
    const int*   dur = (const int*)d_in[1];
    float*       out = (float*)d_out;

    // Recover max_len from out_size (tuple layout vs expanded-only).
    long L;
    int has_tail;
    long os = (long)out_size;
    if ((os - BB) > 0 && ((os - BB) % ((long)BB * (DD + 1))) == 0) {
        L = (os - BB) / ((long)BB * (DD + 1));
        has_tail = 1;
    } else {
        L = os / ((long)BB * DD);
        has_tail = 0;
    }
    if (L <= 0 || L > MAXL) return;

    const int max_len = (int)L;
    const int bpb = (max_len + 31) / 32;   // blocks per batch (32 rows/block)

    float* mel_len_out = out + (long)BB * max_len * DD;   // B floats
    float* mask_out    = mel_len_out + BB;                // B*L floats

    dim3 grid((unsigned)bpb, BB, 1);
    lr_fused_kernel<<<grid, 256>>>(dur, x, out, mel_len_out, mask_out,
                                   max_len, has_tail);
}

// round 15
// speedup vs baseline: 1.0284x; 1.0284x over previous
#include <cuda_runtime.h>

#define BB 32
#define SS 1024
#define DD 512
#define MAXL 8192   // durations in [1,8], S=1024 -> mel_len <= 8192

// 256-bit global load (L1-bypass/nc) and streaming store (sm_100+ PTX v8)
__device__ __forceinline__ void ldg256(const float* p, float* v) {
    asm volatile("ld.global.nc.v8.f32 {%0,%1,%2,%3,%4,%5,%6,%7}, [%8];"
                 : "=f"(v[0]), "=f"(v[1]), "=f"(v[2]), "=f"(v[3]),
                   "=f"(v[4]), "=f"(v[5]), "=f"(v[6]), "=f"(v[7])
                 : "l"(p));
}
__device__ __forceinline__ void stg256_cs(float* p, const float* v) {
    asm volatile("st.global.cs.v8.f32 [%0], {%1,%2,%3,%4,%5,%6,%7,%8};"
                 :: "l"(p),
                    "f"(v[0]), "f"(v[1]), "f"(v[2]), "f"(v[3]),
                    "f"(v[4]), "f"(v[5]), "f"(v[6]), "f"(v[7])
                 : "memory");
}

// warp-level 2-level 32-ary search over smem csum; requires t < mel.
__device__ __forceinline__ int warp_search(const int* s, const int* l1,
                                           int t, int lane)
{
    const int s1 = l1[lane];
    const unsigned m1 = __ballot_sync(0xffffffff, s1 > t);
    const int seg = __ffs(m1) - 1;
    const int s2 = s[(seg << 5) + lane];
    const unsigned m2 = __ballot_sync(0xffffffff, s2 > t);
    return (seg << 5) + __ffs(m2) - 1;   // first i with csum[i] > t
}

// ---------------------------------------------------------------------------
// Single kernel, no inter-block sync. 256 threads = 8 warps; each block
// handles 16 output rows (2 per warp). Both searches are hoisted ahead of
// the payload: one clean batch of 4 LDG.256 (MLP=4), one batch of 4 STG.256.
// ---------------------------------------------------------------------------
__global__ __launch_bounds__(256)
void lr_fused_kernel(const int*   __restrict__ dur,
                     const float* __restrict__ x,
                     float*       __restrict__ out,
                     float*       __restrict__ mel_len_out,
                     float*       __restrict__ mask_out,
                     int max_len, int has_tail)
{
    __shared__ int s[SS];      // inclusive csum of durations[b]
    __shared__ int lvl1[32];   // s[32j+31]
    __shared__ int wsum[8];

    const int b    = blockIdx.y;
    const int tid  = threadIdx.x;
    const int lane = tid & 31;
    const int wid  = tid >> 5;

    // ---- prologue: scan durations[b] into smem (int4/thread) ----
    const int4 d = __ldg(((const int4*)(dur + b * SS)) + tid);
    const int p0 = d.x;
    const int p1 = p0 + d.y;
    const int p2 = p1 + d.z;
    const int p3 = p2 + d.w;
    int tot = p3;
    #pragma unroll
    for (int off = 1; off < 32; off <<= 1) {
        int n = __shfl_up_sync(0xffffffff, tot, off);
        if (lane >= off) tot += n;
    }
    if (lane == 31) wsum[wid] = tot;
    __syncthreads();
    if (wid == 0 && lane < 8) {
        int w = wsum[lane];
        #pragma unroll
        for (int off = 1; off < 8; off <<= 1) {
            int n = __shfl_up_sync(0xff, w, off);
            if (lane >= off) w += n;
        }
        wsum[lane] = w;
    }
    __syncthreads();
    const int base = (tot - p3) + ((wid > 0) ? wsum[wid - 1] : 0);
    s[4 * tid + 0] = base + p0;
    s[4 * tid + 1] = base + p1;
    s[4 * tid + 2] = base + p2;
    s[4 * tid + 3] = base + p3;
    if ((tid & 7) == 7) lvl1[tid >> 3] = base + p3;   // element 32j+31
    __syncthreads();

    // ---- payload: TWO rows per warp ----
    const int t0 = blockIdx.x * 16 + wid * 2;   // rows t0, t0+1
    if (t0 >= max_len) return;
    const int t1 = t0 + 1;
    const bool has1 = t1 < max_len;

    const int mel = lvl1[31];
    const int bS  = b * SS;

    if (has_tail) {
        if (blockIdx.x == 0 && tid == 0) mel_len_out[b] = (float)mel;
        if (lane == 0) {
            mask_out[b * max_len + t0] = (t0 >= mel) ? 1.0f : 0.0f;
            if (has1) mask_out[b * max_len + t1] = (t1 >= mel) ? 1.0f : 0.0f;
        }
    }

    // hoist both searches ahead of all memory traffic
    const int lo0 = (t0 < mel) ? warp_search(s, lvl1, t0, lane) : -1;
    const int lo1 = (has1 && t1 < mel) ? warp_search(s, lvl1, t1, lane) : -1;

    float v0[8] = {0.f,0.f,0.f,0.f,0.f,0.f,0.f,0.f};
    float v1[8] = {0.f,0.f,0.f,0.f,0.f,0.f,0.f,0.f};
    float w0[8] = {0.f,0.f,0.f,0.f,0.f,0.f,0.f,0.f};
    float w1[8] = {0.f,0.f,0.f,0.f,0.f,0.f,0.f,0.f};

    // one clean load batch (up to 4 independent LDG.256)
    if (lo0 >= 0) {
        const float* ib = x + ((long)(bS + lo0)) * DD + lane * 8;
        ldg256(ib,       v0);
        ldg256(ib + 256, v1);
    }
    if (lo1 >= 0) {
        const float* ib = x + ((long)(bS + lo1)) * DD + lane * 8;
        ldg256(ib,       w0);
        ldg256(ib + 256, w1);
    }

    // one clean store batch
    float* ob = out + ((long)(b * max_len + t0)) * DD + lane * 8;
    stg256_cs(ob,       v0);
    stg256_cs(ob + 256, v1);
    if (has1) {
        stg256_cs(ob + DD,       w0);
        stg256_cs(ob + DD + 256, w1);
    }
}

// ---------------------------------------------------------------------------
extern "C" void kernel_launch(void* const* d_in, const int* in_sizes, int n_in,
                              void* d_out, int out_size)
{
    const float* x   = (const float*)d_in[0];
    const int*   dur = (const int*)d_in[1];
    float*       out = (float*)d_out;

    // Recover max_len from out_size (tuple layout vs expanded-only).
    long L;
    int has_tail;
    long os = (long)out_size;
    if ((os - BB) > 0 && ((os - BB) % ((long)BB * (DD + 1))) == 0) {
        L = (os - BB) / ((long)BB * (DD + 1));
        has_tail = 1;
    } else {
        L = os / ((long)BB * DD);
        has_tail = 0;
    }
    if (L <= 0 || L > MAXL) return;

    const int max_len = (int)L;
    const int bpb = (max_len + 15) / 16;   // blocks per batch (16 rows/block)

    float* mel_len_out = out + (long)BB * max_len * DD;   // B floats
    float* mask_out    = mel_len_out + BB;                // B*L floats

    dim3 grid((unsigned)bpb, BB, 1);
    lr_fused_kernel<<<grid, 256>>>(dur, x, out, mel_len_out, mask_out,
                                   max_len, has_tail);
}